// round 6
// baseline (speedup 1.0000x reference)
#include <cuda_runtime.h>
#include <cuda_bf16.h>
#include <math.h>
#include <stdint.h>

// Problem dims
#define CDIM 16
#define PDIM 256
#define DMOD 512
#define DIN  1024
#define DSTATE 16
#define DDT  32
#define NROWS (CDIM*PDIM)          // 4096

typedef unsigned int u32;
typedef __nv_bfloat16 bf16;

// ---------------- scratch (device globals; no allocation allowed) ----------
__device__ float g_xz[NROWS * 2 * DIN];            // in-proj out fp32 [4096,2048]
__device__ float g_xiact[NROWS * DIN];             // gelu(conv) fp32  [4096,1024]
__device__ float g_xdb[NROWS * 64];                // param proj fp32  [4096,64]
__device__ float g_dtlin[NROWS * DIN];             // dt pre-softplus  [4096,1024]

__device__ bf16 g_xh[NROWS * DMOD],        g_xl[NROWS * DMOD];          // x hi/lo
__device__ bf16 g_inwh[2*DIN * DMOD],      g_inwl[2*DIN * DMOD];        // in_w
__device__ bf16 g_xzxh[NROWS * DIN],       g_xzxl[NROWS * DIN];         // in-proj x-branch
__device__ bf16 g_cwth[4 * DIN * DIN],     g_cwtl[4 * DIN * DIN];       // conv_w per-tap [tap][o][i]
__device__ bf16 g_xiah[NROWS * DIN],       g_xial[NROWS * DIN];         // gelu(conv)
__device__ bf16 g_pwh[64 * DIN],           g_pwl[64 * DIN];             // param_w
__device__ bf16 g_dtah[NROWS * 64],        g_dtal[NROWS * 64];          // dt A (pad 64)
__device__ bf16 g_dtwh[DIN * 64],          g_dtwl[DIN * 64];            // dt_w (pad 64)
__device__ bf16 g_yh[NROWS * DIN],         g_yl[NROWS * DIN];           // scan out
__device__ bf16 g_owh[DMOD * DIN],         g_owl[DMOD * DIN];           // out_w

// ------------------------- PTX helpers (arch-generic only) -----------------
__device__ __forceinline__ void ldsm4(u32& r0, u32& r1, u32& r2, u32& r3, u32 addr) {
    asm volatile("ldmatrix.sync.aligned.m8n8.x4.shared.b16 {%0,%1,%2,%3}, [%4];"
                 : "=r"(r0), "=r"(r1), "=r"(r2), "=r"(r3) : "r"(addr));
}
__device__ __forceinline__ void mma16816(float* d, const u32* a, const u32* b) {
    asm volatile(
        "mma.sync.aligned.m16n8k16.row.col.f32.bf16.bf16.f32 "
        "{%0,%1,%2,%3},{%4,%5,%6,%7},{%8,%9},{%0,%1,%2,%3};"
        : "+f"(d[0]), "+f"(d[1]), "+f"(d[2]), "+f"(d[3])
        : "r"(a[0]), "r"(a[1]), "r"(a[2]), "r"(a[3]), "r"(b[0]), "r"(b[1]));
}
__device__ __forceinline__ void cp16(u32 dst, const void* src, int srcsize) {
    asm volatile("cp.async.cg.shared.global [%0], [%1], 16, %2;"
                 :: "r"(dst), "l"(src), "r"(srcsize) : "memory");
}
#define CP_COMMIT() asm volatile("cp.async.commit_group;" ::: "memory")
#define CP_WAIT1()  asm volatile("cp.async.wait_group 1;" ::: "memory")

// 64B-row swizzle: XOR 16B-chunk index (bits 4-5) with row bits (bits 7-8).
#define SW64(o) ((u32)(o) ^ ((((u32)(o)) >> 3) & 0x30))

// --------------------------- math helpers ----------------------------------
__device__ __forceinline__ float gelu_f(float x) {
    float inner = 0.7978845608028654f * fmaf(0.044715f * x, x * x, x);
    return 0.5f * x * (1.0f + tanhf(inner));
}
__device__ __forceinline__ float softplus_f(float x) {
    return fmaxf(x, 0.0f) + log1pf(expf(-fabsf(x)));
}

// ---------------------------------------------------------------------------
// HMMA GEMM (NT): C[M,N] = (Ah+Al)[M,K] @ (Bh+Bl)[N,K]^T + bias[N]
// bf16x3 split: Ah*Bh + Ah*Bl + Al*Bh into fp32 accum (mma.sync m16n8k16).
// BM=BN=128, BK=32, 256 threads (8 warps, 4m x 2n, 32x64 warp tile),
// cp.async 2-stage pipeline, double-buffered B ldmatrix, reordered MMAs.
// flags: 1=gelu, 2=write fp32 C, 4=write bf16 Oh/Ol (cols < ldo), 8=conv mode
// conv mode: K=4096 is 4 taps x 1024; A rows are clamp-shifted xz-x rows,
// B is per-tap transposed conv_w at tap*2^20.
// ---------------------------------------------------------------------------
#define TILE_BYTES 8192                 // 128 rows x 64 B
#define STAGE_BYTES (4 * TILE_BYTES)    // Ah, Al, Bh, Bl
#define GEMM_SMEM (2 * STAGE_BYTES)     // 65536

__device__ __forceinline__ void load_stage(
    u32 sbase, const bf16* __restrict__ Ah, const bf16* __restrict__ Al,
    const bf16* __restrict__ Bh, const bf16* __restrict__ Bl,
    int bm, int bn, int N, int K, int ck, int tid, bool conv)
{
    int tap = 0, kc = ck, ld = K;
    if (conv) { tap = ck >> 5; kc = ck & 31; ld = 1024; }
    const size_t boff = conv ? ((size_t)tap << 20) : 0;
#pragma unroll
    for (int j = 0; j < 2; j++) {
        int linear = tid + j * 256;
        int row = linear >> 2;
        int cc = linear & 3;
        u32 sw = SW64((u32)(row * 64 + cc * 16));
        int grow = bm + row;
        int arow = grow;
        if (conv) {
            int p = (grow & 255) + tap - 2;
            p = p < 0 ? 0 : (p > 255 ? 255 : p);
            arow = (grow & ~255) | p;
        }
        size_t goff = (size_t)arow * ld + kc * 32 + cc * 8;
        cp16(sbase + sw, Ah + goff, 16);
        cp16(sbase + TILE_BYTES + sw, Al + goff, 16);
        int bvalid = (bn + row < N) ? 16 : 0;
        size_t gob = boff + (size_t)(bn + (bvalid ? row : 0)) * ld + kc * 32 + cc * 8;
        cp16(sbase + 2 * TILE_BYTES + sw, Bh + gob, bvalid);
        cp16(sbase + 3 * TILE_BYTES + sw, Bl + gob, bvalid);
    }
}

__global__ __launch_bounds__(256, 2) void gemm_hmma(
    const bf16* __restrict__ Ah, const bf16* __restrict__ Al,
    const bf16* __restrict__ Bh, const bf16* __restrict__ Bl,
    const float* __restrict__ bias, float* __restrict__ C,
    bf16* __restrict__ Oh, bf16* __restrict__ Ol,
    int M, int N, int K, int ldo, int flags)
{
    extern __shared__ __align__(128) char smem[];
    const u32 sb = (u32)__cvta_generic_to_shared(smem);
    const int tid = threadIdx.x;
    const int lane = tid & 31;
    const int wid = tid >> 5;
    const int warp_m = wid & 3;     // * 32
    const int warp_n = wid >> 2;    // * 64
    const bool conv = (flags & 8) != 0;

    const int bm = blockIdx.y * 128;
    const int bn = blockIdx.x * 128;
    const int nch = K >> 5;

    float acc[2][8][4];
#pragma unroll
    for (int mt = 0; mt < 2; mt++)
#pragma unroll
        for (int nt = 0; nt < 8; nt++)
#pragma unroll
            for (int i = 0; i < 4; i++) acc[mt][nt][i] = 0.0f;

    load_stage(sb, Ah, Al, Bh, Bl, bm, bn, N, K, 0, tid, conv);
    CP_COMMIT();
    if (nch > 1) load_stage(sb + STAGE_BYTES, Ah, Al, Bh, Bl, bm, bn, N, K, 1, tid, conv);
    CP_COMMIT();

    // lane-pattern pieces for ldmatrix source addressing
    const int a_row_l = lane & 15;              // row within m16 tile
    const int a_kb    = (lane >> 4) << 4;       // +16B for k8 half
    const int b_row_l = (lane & 7) + ((lane >> 4) << 3);
    const int b_kb    = ((lane >> 3) & 1) << 4;

    for (int ck = 0; ck < nch; ck++) {
        CP_WAIT1();
        __syncthreads();
        const u32 st = sb + (ck & 1) * STAGE_BYTES;

#pragma unroll
        for (int ks = 0; ks < 2; ks++) {
            u32 ah[2][4], al[2][4];
#pragma unroll
            for (int mt = 0; mt < 2; mt++) {
                u32 so = SW64((u32)((warp_m * 32 + mt * 16 + a_row_l) * 64 + ks * 32 + a_kb));
                ldsm4(ah[mt][0], ah[mt][1], ah[mt][2], ah[mt][3], st + so);
                ldsm4(al[mt][0], al[mt][1], al[mt][2], al[mt][3], st + TILE_BYTES + so);
            }
            // double-buffered B: preload nt=0, then load nt+1 while computing nt
            u32 bh[2][4], bl[2][4];
            {
                u32 so = SW64((u32)((warp_n * 64 + b_row_l) * 64 + ks * 32 + b_kb));
                ldsm4(bh[0][0], bh[0][1], bh[0][2], bh[0][3], st + 2 * TILE_BYTES + so);
                ldsm4(bl[0][0], bl[0][1], bl[0][2], bl[0][3], st + 3 * TILE_BYTES + so);
            }
#pragma unroll
            for (int nt = 0; nt < 4; nt++) {
                if (nt < 3) {
                    u32 so = SW64((u32)((warp_n * 64 + (nt + 1) * 16 + b_row_l) * 64 + ks * 32 + b_kb));
                    ldsm4(bh[(nt + 1) & 1][0], bh[(nt + 1) & 1][1],
                          bh[(nt + 1) & 1][2], bh[(nt + 1) & 1][3], st + 2 * TILE_BYTES + so);
                    ldsm4(bl[(nt + 1) & 1][0], bl[(nt + 1) & 1][1],
                          bl[(nt + 1) & 1][2], bl[(nt + 1) & 1][3], st + 3 * TILE_BYTES + so);
                }
                const u32* BH = bh[nt & 1];
                const u32* BL = bl[nt & 1];
                // reordered: consecutive MMAs hit distinct accumulators
                mma16816(acc[0][nt * 2],     ah[0], BH);
                mma16816(acc[0][nt * 2 + 1], ah[0], BH + 2);
                mma16816(acc[1][nt * 2],     ah[1], BH);
                mma16816(acc[1][nt * 2 + 1], ah[1], BH + 2);
                mma16816(acc[0][nt * 2],     ah[0], BL);
                mma16816(acc[0][nt * 2 + 1], ah[0], BL + 2);
                mma16816(acc[1][nt * 2],     ah[1], BL);
                mma16816(acc[1][nt * 2 + 1], ah[1], BL + 2);
                mma16816(acc[0][nt * 2],     al[0], BH);
                mma16816(acc[0][nt * 2 + 1], al[0], BH + 2);
                mma16816(acc[1][nt * 2],     al[1], BH);
                mma16816(acc[1][nt * 2 + 1], al[1], BH + 2);
            }
        }
        __syncthreads();
        if (ck + 2 < nch)
            load_stage(sb + (ck & 1) * STAGE_BYTES, Ah, Al, Bh, Bl, bm, bn, N, K,
                       ck + 2, tid, conv);
        CP_COMMIT();
    }

    // epilogue
#pragma unroll
    for (int mt = 0; mt < 2; mt++) {
#pragma unroll
        for (int nt = 0; nt < 8; nt++) {
            int row0 = bm + warp_m * 32 + mt * 16 + (lane >> 2);
            int col = bn + warp_n * 64 + nt * 8 + (lane & 3) * 2;
            if (col < N) {
                float b0 = __ldg(bias + col), b1 = __ldg(bias + col + 1);
                float v00 = acc[mt][nt][0] + b0, v01 = acc[mt][nt][1] + b1;
                float v10 = acc[mt][nt][2] + b0, v11 = acc[mt][nt][3] + b1;
                if (flags & 1) {
                    v00 = gelu_f(v00); v01 = gelu_f(v01);
                    v10 = gelu_f(v10); v11 = gelu_f(v11);
                }
                if (flags & 2) {
                    *(float2*)(C + (size_t)row0 * N + col) = make_float2(v00, v01);
                    *(float2*)(C + (size_t)(row0 + 8) * N + col) = make_float2(v10, v11);
                }
                if ((flags & 4) && col < ldo) {
                    bf16 h00 = __float2bfloat16(v00), h01 = __float2bfloat16(v01);
                    bf16 h10 = __float2bfloat16(v10), h11 = __float2bfloat16(v11);
                    *(__nv_bfloat162*)(Oh + (size_t)row0 * ldo + col) = __nv_bfloat162(h00, h01);
                    *(__nv_bfloat162*)(Oh + (size_t)(row0 + 8) * ldo + col) = __nv_bfloat162(h10, h11);
                    bf16 l00 = __float2bfloat16(v00 - __bfloat162float(h00));
                    bf16 l01 = __float2bfloat16(v01 - __bfloat162float(h01));
                    bf16 l10 = __float2bfloat16(v10 - __bfloat162float(h10));
                    bf16 l11 = __float2bfloat16(v11 - __bfloat162float(h11));
                    *(__nv_bfloat162*)(Ol + (size_t)row0 * ldo + col) = __nv_bfloat162(l00, l01);
                    *(__nv_bfloat162*)(Ol + (size_t)(row0 + 8) * ldo + col) = __nv_bfloat162(l10, l11);
                }
            }
        }
    }
}

// ---------------------------------------------------------------------------
// fp32 -> bf16 hi/lo split (elementwise, float4 vectorized)
// ---------------------------------------------------------------------------
__global__ void cvt_hilo(const float* __restrict__ src, bf16* __restrict__ hi,
                         bf16* __restrict__ lo, int n4)
{
    int gid = blockIdx.x * blockDim.x + threadIdx.x;
    if (gid >= n4) return;
    float4 v = *(const float4*)(src + gid * 4);
    float a[4] = {v.x, v.y, v.z, v.w};
    bf16 h[4], l[4];
#pragma unroll
    for (int i = 0; i < 4; i++) {
        h[i] = __float2bfloat16(a[i]);
        l[i] = __float2bfloat16(a[i] - __bfloat162float(h[i]));
    }
    *(__nv_bfloat162*)(hi + gid * 4)     = __nv_bfloat162(h[0], h[1]);
    *(__nv_bfloat162*)(hi + gid * 4 + 2) = __nv_bfloat162(h[2], h[3]);
    *(__nv_bfloat162*)(lo + gid * 4)     = __nv_bfloat162(l[0], l[1]);
    *(__nv_bfloat162*)(lo + gid * 4 + 2) = __nv_bfloat162(l[2], l[3]);
}

// padded variant: out[row,k] = (k < cols ? src[row*src_ld+k] : 0), outK wide
__global__ void cvt_pad(const float* __restrict__ src, bf16* __restrict__ hi,
                        bf16* __restrict__ lo, int rows, int src_ld, int cols, int outK)
{
    int gid = blockIdx.x * blockDim.x + threadIdx.x;
    if (gid >= rows * outK) return;
    int k = gid % outK, r = gid / outK;
    float v = (k < cols) ? src[(size_t)r * src_ld + k] : 0.0f;
    bf16 h = __float2bfloat16(v);
    hi[gid] = h;
    lo[gid] = __float2bfloat16(v - __bfloat162float(h));
}

// conv_w[o,i,h] -> per-tap transposed hi/lo: dst[tap*2^20 + o*1024 + i]
__global__ void cvt_convw_taps(const float* __restrict__ cw, bf16* __restrict__ hi,
                               bf16* __restrict__ lo)
{
    int gid = blockIdx.x * blockDim.x + threadIdx.x;
    if (gid >= 4 * DIN * DIN) return;
    int tap = gid >> 20;
    int oi = gid & 0xFFFFF;
    float v = cw[(size_t)oi * 4 + tap];
    bf16 h = __float2bfloat16(v);
    hi[gid] = h;
    lo[gid] = __float2bfloat16(v - __bfloat162float(h));
}

// ---------------------------------------------------------------------------
// Selective scan. Grid = C*(DI/64) = 256 blocks x 256 threads.
// B/C params for the chunk preloaded to smem; per-step inputs prefetched.
// ---------------------------------------------------------------------------
__global__ __launch_bounds__(256) void scan_kernel(
    const float* __restrict__ xiact, const float* __restrict__ xz,
    const float* __restrict__ dtlin, const float* __restrict__ xdb,
    const float* __restrict__ A_log, const float* __restrict__ Dp,
    const float* __restrict__ ssm0, bf16* __restrict__ yh, bf16* __restrict__ yl,
    float* __restrict__ state_out)
{
    __shared__ float bcs[PDIM][32];
    const int tid = threadIdx.x;
    const int q = tid & 3;
    const int dl = tid >> 2;
    const int c = blockIdx.x >> 4;
    const int d = ((blockIdx.x & 15) << 6) + dl;

    for (int i = tid; i < PDIM * 32; i += 256) {
        int p = i >> 5, n = i & 31;
        bcs[p][n] = xdb[(size_t)((c << 8) + p) * 64 + 32 + n];
    }

    float An[4], s[4];
#pragma unroll
    for (int j = 0; j < 4; j++) {
        int n = q * 4 + j;
        An[j] = -expf(A_log[d * DSTATE + n]);
        s[j] = ssm0[((size_t)c * DIN + d) * DSTATE + n];
    }
    const float Dd = Dp[d];
    __syncthreads();

    const size_t row0 = (size_t)(c << 8);
    // prefetch step 0
    float dtc = dtlin[row0 * DIN + d];
    float xvc = xiact[row0 * DIN + d];
    float zvc = xz[row0 * (2 * DIN) + DIN + d];

    for (int p = 0; p < PDIM; p++) {
        float dtn = 0.f, xvn = 0.f, zvn = 0.f;
        if (p + 1 < PDIM) {
            size_t r = (row0 + p + 1);
            dtn = dtlin[r * DIN + d];
            xvn = xiact[r * DIN + d];
            zvn = xz[r * (2 * DIN) + DIN + d];
        }
        float dtv = softplus_f(dtc);
        float xdt = xvc * dtv;
        float y = 0.0f;
#pragma unroll
        for (int j = 0; j < 4; j++) {
            int n = q * 4 + j;
            float dA = expf(dtv * An[j]);
            s[j] = fmaf(s[j], dA, xdt * bcs[p][n]);
            y = fmaf(s[j], bcs[p][16 + n], y);
        }
        y += __shfl_xor_sync(0xffffffffu, y, 1);
        y += __shfl_xor_sync(0xffffffffu, y, 2);
        if (q == 0) {
            float r = (y + Dd * xvc) * gelu_f(gelu_f(zvc));  // double gelu (faithful)
            bf16 h = __float2bfloat16(r);
            yh[(row0 + p) * DIN + d] = h;
            yl[(row0 + p) * DIN + d] = __float2bfloat16(r - __bfloat162float(h));
        }
        dtc = dtn; xvc = xvn; zvc = zvn;
    }

    if (state_out) {
#pragma unroll
        for (int j = 0; j < 4; j++)
            state_out[((size_t)c * DIN + d) * DSTATE + q * 4 + j] = s[j];
    }
}

// ---------------------------------------------------------------------------
extern "C" void kernel_launch(void* const* d_in, const int* in_sizes, int n_in,
                              void* d_out, int out_size)
{
    const float* x       = (const float*)d_in[0];
    const float* ssm0    = (const float*)d_in[1];
    const float* in_w    = (const float*)d_in[2];
    const float* in_b    = (const float*)d_in[3];
    const float* conv_w  = (const float*)d_in[4];
    const float* conv_b  = (const float*)d_in[5];
    const float* param_w = (const float*)d_in[6];
    const float* param_b = (const float*)d_in[7];
    const float* dt_w    = (const float*)d_in[8];
    const float* dt_b    = (const float*)d_in[9];
    const float* out_w   = (const float*)d_in[10];
    const float* out_b   = (const float*)d_in[11];
    const float* A_log   = (const float*)d_in[12];
    const float* Dp      = (const float*)d_in[13];
    float* out = (float*)d_out;

    static int smem_set = 0;
    if (!smem_set) {
        cudaFuncSetAttribute(gemm_hmma, cudaFuncAttributeMaxDynamicSharedMemorySize,
                             GEMM_SMEM);
        smem_set = 1;
    }

    float *p_xz, *p_xiact, *p_xdb, *p_dtlin;
    cudaGetSymbolAddress((void**)&p_xz, g_xz);
    cudaGetSymbolAddress((void**)&p_xiact, g_xiact);
    cudaGetSymbolAddress((void**)&p_xdb, g_xdb);
    cudaGetSymbolAddress((void**)&p_dtlin, g_dtlin);
    bf16 *xh, *xl, *inwh, *inwl, *xzxh, *xzxl, *cwth, *cwtl, *xiah, *xial;
    bf16 *pwh, *pwl, *dtah, *dtal, *dtwh, *dtwl, *yh, *yl, *owh, *owl;
    cudaGetSymbolAddress((void**)&xh, g_xh);     cudaGetSymbolAddress((void**)&xl, g_xl);
    cudaGetSymbolAddress((void**)&inwh, g_inwh); cudaGetSymbolAddress((void**)&inwl, g_inwl);
    cudaGetSymbolAddress((void**)&xzxh, g_xzxh); cudaGetSymbolAddress((void**)&xzxl, g_xzxl);
    cudaGetSymbolAddress((void**)&cwth, g_cwth); cudaGetSymbolAddress((void**)&cwtl, g_cwtl);
    cudaGetSymbolAddress((void**)&xiah, g_xiah); cudaGetSymbolAddress((void**)&xial, g_xial);
    cudaGetSymbolAddress((void**)&pwh, g_pwh);   cudaGetSymbolAddress((void**)&pwl, g_pwl);
    cudaGetSymbolAddress((void**)&dtah, g_dtah); cudaGetSymbolAddress((void**)&dtal, g_dtal);
    cudaGetSymbolAddress((void**)&dtwh, g_dtwh); cudaGetSymbolAddress((void**)&dtwl, g_dtwl);
    cudaGetSymbolAddress((void**)&yh, g_yh);     cudaGetSymbolAddress((void**)&yl, g_yl);
    cudaGetSymbolAddress((void**)&owh, g_owh);   cudaGetSymbolAddress((void**)&owl, g_owl);

    const int y_elems = NROWS * DMOD;
    const int s_elems = CDIM * DIN * DSTATE;
    float* state_out = (out_size >= y_elems + s_elems) ? (out + y_elems) : nullptr;

    // launch order chosen so ncu -s 5 captures the conv GEMM (launch #5)
    // 0-3: conversions needed before in-proj + conv
    cvt_hilo<<<(NROWS * DMOD / 4 + 255) / 256, 256>>>(x, xh, xl, NROWS * DMOD / 4);
    cvt_hilo<<<(2 * DIN * DMOD / 4 + 255) / 256, 256>>>(in_w, inwh, inwl, 2 * DIN * DMOD / 4);
    cvt_convw_taps<<<(4 * DIN * DIN) / 256, 256>>>(conv_w, cwth, cwtl);
    cvt_hilo<<<(64 * DIN / 4 + 255) / 256, 256>>>(param_w, pwh, pwl, 64 * DIN / 4);

    // 4) in-proj: xz = x @ in_w^T + in_b  [4096,2048] fp32 + x-branch hi/lo
    gemm_hmma<<<dim3(2048 / 128, NROWS / 128), 256, GEMM_SMEM>>>(
        xh, xl, inwh, inwl, in_b, p_xz, xzxh, xzxl, NROWS, 2048, DMOD, DIN, 2 | 4);

    // 5) conv (direct 4-tap) + bias + gelu -> xiact fp32 AND hi/lo  [4096,1024]
    gemm_hmma<<<dim3(DIN / 128, NROWS / 128), 256, GEMM_SMEM>>>(
        xzxh, xzxl, cwth, cwtl, conv_b, p_xiact, xiah, xial,
        NROWS, DIN, 4 * DIN, DIN, 1 | 2 | 4 | 8);

    // 6) param proj: xdb = xi @ param_w^T + param_b   [4096,64], K=1024
    gemm_hmma<<<dim3(1, NROWS / 128), 256, GEMM_SMEM>>>(
        xiah, xial, pwh, pwl, param_b, p_xdb, nullptr, nullptr, NROWS, 64, DIN, 0, 2);

    // 7-8) dt operand conversions
    cvt_pad<<<(DIN * 64 + 255) / 256, 256>>>(dt_w, dtwh, dtwl, DIN, DDT, DDT, 64);
    cvt_pad<<<(NROWS * 64 + 255) / 256, 256>>>(p_xdb, dtah, dtal, NROWS, 64, DDT, 64);

    // 9) dt proj: dtlin = dt @ dt_w^T + dt_b   [4096,1024], K=64(padded)
    gemm_hmma<<<dim3(DIN / 128, NROWS / 128), 256, GEMM_SMEM>>>(
        dtah, dtal, dtwh, dtwl, dt_b, p_dtlin, nullptr, nullptr, NROWS, DIN, 64, 0, 2);

    // 10) selective scan -> ypre hi/lo + final state
    scan_kernel<<<256, 256>>>(p_xiact, p_xz, p_dtlin, p_xdb, A_log, Dp, ssm0,
                              yh, yl, state_out);

    // 11) out_w conversion
    cvt_hilo<<<(DMOD * DIN / 4 + 255) / 256, 256>>>(out_w, owh, owl, DMOD * DIN / 4);

    // 12) out proj: y @ out_w^T + out_b -> d_out   [4096,512], K=1024
    gemm_hmma<<<dim3(DMOD / 128, NROWS / 128), 256, GEMM_SMEM>>>(
        yh, yl, owh, owl, out_b, out, nullptr, nullptr, NROWS, DMOD, DIN, 0, 2);
}

// round 7
// speedup vs baseline: 1.4797x; 1.4797x over previous
#include <cuda_runtime.h>
#include <cuda_bf16.h>
#include <math.h>
#include <stdint.h>

// Problem dims
#define CDIM 16
#define PDIM 256
#define DMOD 512
#define DIN  1024
#define DSTATE 16
#define DDT  32
#define NROWS (CDIM*PDIM)          // 4096

typedef unsigned int u32;
typedef __nv_bfloat16 bf16;

// ---------------- scratch (device globals; no allocation allowed) ----------
__device__ float g_xz[NROWS * 2 * DIN];            // in-proj out fp32 [4096,2048]
__device__ float g_xiact[NROWS * DIN];             // gelu(conv) fp32  [4096,1024]
__device__ float g_xdb[NROWS * 64];                // param proj fp32  [4096,64]
__device__ float g_dtlin[NROWS * DIN];             // dt pre-softplus  [4096,1024]

__device__ bf16 g_xh[NROWS * DMOD],        g_xl[NROWS * DMOD];          // x hi/lo
__device__ bf16 g_inwh[2*DIN * DMOD],      g_inwl[2*DIN * DMOD];        // in_w
__device__ bf16 g_xzxh[NROWS * DIN],       g_xzxl[NROWS * DIN];         // in-proj x-branch
__device__ bf16 g_cwth[4 * DIN * DIN],     g_cwtl[4 * DIN * DIN];       // conv_w per-tap [tap][o][i]
__device__ bf16 g_xiah[NROWS * DIN],       g_xial[NROWS * DIN];         // gelu(conv)
__device__ bf16 g_pwh[64 * DIN],           g_pwl[64 * DIN];             // param_w
__device__ bf16 g_dtah[NROWS * 64],        g_dtal[NROWS * 64];          // dt A (pad 64)
__device__ bf16 g_dtwh[DIN * 64],          g_dtwl[DIN * 64];            // dt_w (pad 64)
__device__ bf16 g_yh[NROWS * DIN],         g_yl[NROWS * DIN];           // scan out
__device__ bf16 g_owh[DMOD * DIN],         g_owl[DMOD * DIN];           // out_w

// ------------------------- PTX helpers (arch-generic only) -----------------
__device__ __forceinline__ void ldsm4(u32& r0, u32& r1, u32& r2, u32& r3, u32 addr) {
    asm volatile("ldmatrix.sync.aligned.m8n8.x4.shared.b16 {%0,%1,%2,%3}, [%4];"
                 : "=r"(r0), "=r"(r1), "=r"(r2), "=r"(r3) : "r"(addr));
}
__device__ __forceinline__ void mma16816(float* d, const u32* a, const u32* b) {
    asm volatile(
        "mma.sync.aligned.m16n8k16.row.col.f32.bf16.bf16.f32 "
        "{%0,%1,%2,%3},{%4,%5,%6,%7},{%8,%9},{%0,%1,%2,%3};"
        : "+f"(d[0]), "+f"(d[1]), "+f"(d[2]), "+f"(d[3])
        : "r"(a[0]), "r"(a[1]), "r"(a[2]), "r"(a[3]), "r"(b[0]), "r"(b[1]));
}
__device__ __forceinline__ void cp16(u32 dst, const void* src, int srcsize) {
    asm volatile("cp.async.cg.shared.global [%0], [%1], 16, %2;"
                 :: "r"(dst), "l"(src), "r"(srcsize) : "memory");
}
#define CP_COMMIT() asm volatile("cp.async.commit_group;" ::: "memory")
#define CP_WAIT1()  asm volatile("cp.async.wait_group 1;" ::: "memory")

// 64B-row swizzle: XOR 16B-chunk index (bits 4-5) with row bits (bits 7-8).
#define SW64(o) ((u32)(o) ^ ((((u32)(o)) >> 3) & 0x30))

// --------------------------- math helpers ----------------------------------
__device__ __forceinline__ float gelu_f(float x) {
    float inner = 0.7978845608028654f * fmaf(0.044715f * x, x * x, x);
    return 0.5f * x * (1.0f + tanhf(inner));
}
__device__ __forceinline__ float softplus_f(float x) {
    return fmaxf(x, 0.0f) + log1pf(expf(-fabsf(x)));
}
__device__ __forceinline__ void split_hilo(float v, bf16& h, bf16& l) {
    h = __float2bfloat16(v);
    l = __float2bfloat16(v - __bfloat162float(h));
}

// ---------------------------------------------------------------------------
// HMMA GEMM (NT): C[M,N] = (Ah+Al)[M,K] @ (Bh+Bl)[N,K]^T + bias[N]
// bf16x3 split: Ah*Bh + Ah*Bl + Al*Bh into fp32 accum (mma.sync m16n8k16).
// BM=BN=128, BK=32, 256 threads (8 warps, 4m x 2n, 32x64 warp tile),
// cp.async 2-stage pipeline. R4-exact mainloop (known-good 762us config).
// flags: 1=gelu, 2=write fp32 C, 4=write bf16 Oh/Ol (cols < ldo), 8=conv mode
// conv mode: K=4096 is 4 taps x 1024; A rows are clamp-shifted xz-x rows,
// B is per-tap transposed conv_w at tap*2^20.
// ---------------------------------------------------------------------------
#define TILE_BYTES 8192                 // 128 rows x 64 B
#define STAGE_BYTES (4 * TILE_BYTES)    // Ah, Al, Bh, Bl
#define GEMM_SMEM (2 * STAGE_BYTES)     // 65536

__device__ __forceinline__ void load_stage(
    u32 sbase, const bf16* __restrict__ Ah, const bf16* __restrict__ Al,
    const bf16* __restrict__ Bh, const bf16* __restrict__ Bl,
    int bm, int bn, int N, int K, int ck, int tid, bool conv)
{
    int tap = 0, kc = ck, ld = K;
    if (conv) { tap = ck >> 5; kc = ck & 31; ld = 1024; }
    const size_t boff = conv ? ((size_t)tap << 20) : 0;
#pragma unroll
    for (int j = 0; j < 2; j++) {
        int linear = tid + j * 256;
        int row = linear >> 2;
        int cc = linear & 3;
        u32 sw = SW64((u32)(row * 64 + cc * 16));
        int grow = bm + row;
        int arow = grow;
        if (conv) {
            int p = (grow & 255) + tap - 2;
            p = p < 0 ? 0 : (p > 255 ? 255 : p);
            arow = (grow & ~255) | p;
        }
        size_t goff = (size_t)arow * ld + kc * 32 + cc * 8;
        cp16(sbase + sw, Ah + goff, 16);
        cp16(sbase + TILE_BYTES + sw, Al + goff, 16);
        int bvalid = (bn + row < N) ? 16 : 0;
        size_t gob = boff + (size_t)(bn + (bvalid ? row : 0)) * ld + kc * 32 + cc * 8;
        cp16(sbase + 2 * TILE_BYTES + sw, Bh + gob, bvalid);
        cp16(sbase + 3 * TILE_BYTES + sw, Bl + gob, bvalid);
    }
}

__global__ __launch_bounds__(256) void gemm_hmma(
    const bf16* __restrict__ Ah, const bf16* __restrict__ Al,
    const bf16* __restrict__ Bh, const bf16* __restrict__ Bl,
    const float* __restrict__ bias, float* __restrict__ C,
    bf16* __restrict__ Oh, bf16* __restrict__ Ol,
    int M, int N, int K, int ldo, int flags)
{
    extern __shared__ __align__(128) char smem[];
    const u32 sb = (u32)__cvta_generic_to_shared(smem);
    const int tid = threadIdx.x;
    const int lane = tid & 31;
    const int wid = tid >> 5;
    const int warp_m = wid & 3;     // * 32
    const int warp_n = wid >> 2;    // * 64
    const bool conv = (flags & 8) != 0;

    const int bm = blockIdx.y * 128;
    const int bn = blockIdx.x * 128;
    const int nch = K >> 5;

    float acc[2][8][4];
#pragma unroll
    for (int mt = 0; mt < 2; mt++)
#pragma unroll
        for (int nt = 0; nt < 8; nt++)
#pragma unroll
            for (int i = 0; i < 4; i++) acc[mt][nt][i] = 0.0f;

    load_stage(sb, Ah, Al, Bh, Bl, bm, bn, N, K, 0, tid, conv);
    CP_COMMIT();
    if (nch > 1) load_stage(sb + STAGE_BYTES, Ah, Al, Bh, Bl, bm, bn, N, K, 1, tid, conv);
    CP_COMMIT();

    // lane-pattern pieces for ldmatrix source addressing
    const int a_row_l = lane & 15;              // row within m16 tile
    const int a_kb    = (lane >> 4) << 4;       // +16B for k8 half
    const int b_row_l = (lane & 7) + ((lane >> 4) << 3);
    const int b_kb    = ((lane >> 3) & 1) << 4;

    for (int ck = 0; ck < nch; ck++) {
        CP_WAIT1();
        __syncthreads();
        const u32 st = sb + (ck & 1) * STAGE_BYTES;

#pragma unroll
        for (int ks = 0; ks < 2; ks++) {
            u32 ah[2][4], al[2][4];
#pragma unroll
            for (int mt = 0; mt < 2; mt++) {
                u32 so = SW64((u32)((warp_m * 32 + mt * 16 + a_row_l) * 64 + ks * 32 + a_kb));
                ldsm4(ah[mt][0], ah[mt][1], ah[mt][2], ah[mt][3], st + so);
                ldsm4(al[mt][0], al[mt][1], al[mt][2], al[mt][3], st + TILE_BYTES + so);
            }
#pragma unroll
            for (int nt16 = 0; nt16 < 4; nt16++) {
                u32 so = SW64((u32)((warp_n * 64 + nt16 * 16 + b_row_l) * 64 + ks * 32 + b_kb));
                u32 bh[4], bl[4];
                ldsm4(bh[0], bh[1], bh[2], bh[3], st + 2 * TILE_BYTES + so);
                ldsm4(bl[0], bl[1], bl[2], bl[3], st + 3 * TILE_BYTES + so);
#pragma unroll
                for (int mt = 0; mt < 2; mt++) {
                    mma16816(acc[mt][nt16 * 2], ah[mt], bh);
                    mma16816(acc[mt][nt16 * 2], ah[mt], bl);
                    mma16816(acc[mt][nt16 * 2], al[mt], bh);
                    mma16816(acc[mt][nt16 * 2 + 1], ah[mt], bh + 2);
                    mma16816(acc[mt][nt16 * 2 + 1], ah[mt], bl + 2);
                    mma16816(acc[mt][nt16 * 2 + 1], al[mt], bh + 2);
                }
            }
        }
        __syncthreads();
        if (ck + 2 < nch)
            load_stage(sb + (ck & 1) * STAGE_BYTES, Ah, Al, Bh, Bl, bm, bn, N, K,
                       ck + 2, tid, conv);
        CP_COMMIT();
    }

    // epilogue
#pragma unroll
    for (int mt = 0; mt < 2; mt++) {
#pragma unroll
        for (int nt = 0; nt < 8; nt++) {
            int row0 = bm + warp_m * 32 + mt * 16 + (lane >> 2);
            int col = bn + warp_n * 64 + nt * 8 + (lane & 3) * 2;
            if (col < N) {
                float b0 = __ldg(bias + col), b1 = __ldg(bias + col + 1);
                float v00 = acc[mt][nt][0] + b0, v01 = acc[mt][nt][1] + b1;
                float v10 = acc[mt][nt][2] + b0, v11 = acc[mt][nt][3] + b1;
                if (flags & 1) {
                    v00 = gelu_f(v00); v01 = gelu_f(v01);
                    v10 = gelu_f(v10); v11 = gelu_f(v11);
                }
                if (flags & 2) {
                    *(float2*)(C + (size_t)row0 * N + col) = make_float2(v00, v01);
                    *(float2*)(C + (size_t)(row0 + 8) * N + col) = make_float2(v10, v11);
                }
                if ((flags & 4) && col < ldo) {
                    bf16 h00, h01, h10, h11, l00, l01, l10, l11;
                    split_hilo(v00, h00, l00); split_hilo(v01, h01, l01);
                    split_hilo(v10, h10, l10); split_hilo(v11, h11, l11);
                    *(__nv_bfloat162*)(Oh + (size_t)row0 * ldo + col) = __nv_bfloat162(h00, h01);
                    *(__nv_bfloat162*)(Oh + (size_t)(row0 + 8) * ldo + col) = __nv_bfloat162(h10, h11);
                    *(__nv_bfloat162*)(Ol + (size_t)row0 * ldo + col) = __nv_bfloat162(l00, l01);
                    *(__nv_bfloat162*)(Ol + (size_t)(row0 + 8) * ldo + col) = __nv_bfloat162(l10, l11);
                }
            }
        }
    }
}

// ---------------------------------------------------------------------------
// Fused prep: converts x, in_w (vec4 flat) and conv_w (per-tap transpose)
// in ONE launch so the profiled launch slot lands on the conv GEMM.
// ---------------------------------------------------------------------------
#define PREP_N0 (NROWS * DMOD / 4)        // 524288  x (vec4)
#define PREP_N1 (2 * DIN * DMOD / 4)      // 262144  in_w (vec4)
#define PREP_N2 (4 * DIN * DIN)           // 4194304 conv_w taps (scalar)
#define PREP_TOTAL (PREP_N0 + PREP_N1 + PREP_N2)

__global__ void prep_all(const float* __restrict__ x, const float* __restrict__ in_w,
                         const float* __restrict__ cw,
                         bf16* __restrict__ xh, bf16* __restrict__ xl,
                         bf16* __restrict__ inwh, bf16* __restrict__ inwl,
                         bf16* __restrict__ cwth, bf16* __restrict__ cwtl)
{
    int gid = blockIdx.x * blockDim.x + threadIdx.x;
    if (gid < PREP_N0 + PREP_N1) {
        const float* src = (gid < PREP_N0) ? x : in_w;
        bf16* hi = (gid < PREP_N0) ? xh : inwh;
        bf16* lo = (gid < PREP_N0) ? xl : inwl;
        int g = (gid < PREP_N0) ? gid : gid - PREP_N0;
        float4 v = *(const float4*)(src + (size_t)g * 4);
        float a[4] = {v.x, v.y, v.z, v.w};
        bf16 h[4], l[4];
#pragma unroll
        for (int i = 0; i < 4; i++) split_hilo(a[i], h[i], l[i]);
        *(__nv_bfloat162*)(hi + (size_t)g * 4)     = __nv_bfloat162(h[0], h[1]);
        *(__nv_bfloat162*)(hi + (size_t)g * 4 + 2) = __nv_bfloat162(h[2], h[3]);
        *(__nv_bfloat162*)(lo + (size_t)g * 4)     = __nv_bfloat162(l[0], l[1]);
        *(__nv_bfloat162*)(lo + (size_t)g * 4 + 2) = __nv_bfloat162(l[2], l[3]);
    } else if (gid < PREP_TOTAL) {
        int g = gid - PREP_N0 - PREP_N1;     // [tap][o][i]
        int tap = g >> 20;
        int oi = g & 0xFFFFF;
        float v = cw[(size_t)oi * 4 + tap];
        bf16 h, l;
        split_hilo(v, h, l);
        cwth[g] = h;
        cwtl[g] = l;
    }
}

// padded variant: out[row,k] = (k < cols ? src[row*src_ld+k] : 0), outK wide
__global__ void cvt_pad(const float* __restrict__ src, bf16* __restrict__ hi,
                        bf16* __restrict__ lo, int rows, int src_ld, int cols, int outK)
{
    int gid = blockIdx.x * blockDim.x + threadIdx.x;
    if (gid >= rows * outK) return;
    int k = gid % outK, r = gid / outK;
    float v = (k < cols) ? src[(size_t)r * src_ld + k] : 0.0f;
    bf16 h, l;
    split_hilo(v, h, l);
    hi[gid] = h;
    lo[gid] = l;
}

// flat fp32 -> hi/lo (vec4)
__global__ void cvt_hilo(const float* __restrict__ src, bf16* __restrict__ hi,
                         bf16* __restrict__ lo, int n4)
{
    int gid = blockIdx.x * blockDim.x + threadIdx.x;
    if (gid >= n4) return;
    float4 v = *(const float4*)(src + (size_t)gid * 4);
    float a[4] = {v.x, v.y, v.z, v.w};
    bf16 h[4], l[4];
#pragma unroll
    for (int i = 0; i < 4; i++) split_hilo(a[i], h[i], l[i]);
    *(__nv_bfloat162*)(hi + (size_t)gid * 4)     = __nv_bfloat162(h[0], h[1]);
    *(__nv_bfloat162*)(hi + (size_t)gid * 4 + 2) = __nv_bfloat162(h[2], h[3]);
    *(__nv_bfloat162*)(lo + (size_t)gid * 4)     = __nv_bfloat162(l[0], l[1]);
    *(__nv_bfloat162*)(lo + (size_t)gid * 4 + 2) = __nv_bfloat162(l[2], l[3]);
}

// ---------------------------------------------------------------------------
// Selective scan. Grid = C*(DI/64) = 256 blocks x 256 threads.
// ---------------------------------------------------------------------------
__global__ __launch_bounds__(256) void scan_kernel(
    const float* __restrict__ xiact, const float* __restrict__ xz,
    const float* __restrict__ dtlin, const float* __restrict__ xdb,
    const float* __restrict__ A_log, const float* __restrict__ Dp,
    const float* __restrict__ ssm0, bf16* __restrict__ yh, bf16* __restrict__ yl,
    float* __restrict__ state_out)
{
    __shared__ float bcs[PDIM][32];
    const int tid = threadIdx.x;
    const int q = tid & 3;
    const int dl = tid >> 2;
    const int c = blockIdx.x >> 4;
    const int d = ((blockIdx.x & 15) << 6) + dl;

    for (int i = tid; i < PDIM * 32; i += 256) {
        int p = i >> 5, n = i & 31;
        bcs[p][n] = xdb[(size_t)((c << 8) + p) * 64 + 32 + n];
    }

    float An[4], s[4];
#pragma unroll
    for (int j = 0; j < 4; j++) {
        int n = q * 4 + j;
        An[j] = -expf(A_log[d * DSTATE + n]);
        s[j] = ssm0[((size_t)c * DIN + d) * DSTATE + n];
    }
    const float Dd = Dp[d];
    __syncthreads();

    const size_t row0 = (size_t)(c << 8);
    float dtc = dtlin[row0 * DIN + d];
    float xvc = xiact[row0 * DIN + d];
    float zvc = xz[row0 * (2 * DIN) + DIN + d];

    for (int p = 0; p < PDIM; p++) {
        float dtn = 0.f, xvn = 0.f, zvn = 0.f;
        if (p + 1 < PDIM) {
            size_t r = row0 + p + 1;
            dtn = dtlin[r * DIN + d];
            xvn = xiact[r * DIN + d];
            zvn = xz[r * (2 * DIN) + DIN + d];
        }
        float dtv = softplus_f(dtc);
        float xdt = xvc * dtv;
        float y = 0.0f;
#pragma unroll
        for (int j = 0; j < 4; j++) {
            int n = q * 4 + j;
            float dA = expf(dtv * An[j]);
            s[j] = fmaf(s[j], dA, xdt * bcs[p][n]);
            y = fmaf(s[j], bcs[p][16 + n], y);
        }
        y += __shfl_xor_sync(0xffffffffu, y, 1);
        y += __shfl_xor_sync(0xffffffffu, y, 2);
        if (q == 0) {
            float r = (y + Dd * xvc) * gelu_f(gelu_f(zvc));  // double gelu (faithful)
            bf16 h, l;
            split_hilo(r, h, l);
            yh[(row0 + p) * DIN + d] = h;
            yl[(row0 + p) * DIN + d] = l;
        }
        dtc = dtn; xvc = xvn; zvc = zvn;
    }

    if (state_out) {
#pragma unroll
        for (int j = 0; j < 4; j++)
            state_out[((size_t)c * DIN + d) * DSTATE + q * 4 + j] = s[j];
    }
}

// ---------------------------------------------------------------------------
extern "C" void kernel_launch(void* const* d_in, const int* in_sizes, int n_in,
                              void* d_out, int out_size)
{
    const float* x       = (const float*)d_in[0];
    const float* ssm0    = (const float*)d_in[1];
    const float* in_w    = (const float*)d_in[2];
    const float* in_b    = (const float*)d_in[3];
    const float* conv_w  = (const float*)d_in[4];
    const float* conv_b  = (const float*)d_in[5];
    const float* param_w = (const float*)d_in[6];
    const float* param_b = (const float*)d_in[7];
    const float* dt_w    = (const float*)d_in[8];
    const float* dt_b    = (const float*)d_in[9];
    const float* out_w   = (const float*)d_in[10];
    const float* out_b   = (const float*)d_in[11];
    const float* A_log   = (const float*)d_in[12];
    const float* Dp      = (const float*)d_in[13];
    float* out = (float*)d_out;

    static int smem_set = 0;
    if (!smem_set) {
        cudaFuncSetAttribute(gemm_hmma, cudaFuncAttributeMaxDynamicSharedMemorySize,
                             GEMM_SMEM);
        smem_set = 1;
    }

    float *p_xz, *p_xiact, *p_xdb, *p_dtlin;
    cudaGetSymbolAddress((void**)&p_xz, g_xz);
    cudaGetSymbolAddress((void**)&p_xiact, g_xiact);
    cudaGetSymbolAddress((void**)&p_xdb, g_xdb);
    cudaGetSymbolAddress((void**)&p_dtlin, g_dtlin);
    bf16 *xh, *xl, *inwh, *inwl, *xzxh, *xzxl, *cwth, *cwtl, *xiah, *xial;
    bf16 *pwh, *pwl, *dtah, *dtal, *dtwh, *dtwl, *yh, *yl, *owh, *owl;
    cudaGetSymbolAddress((void**)&xh, g_xh);     cudaGetSymbolAddress((void**)&xl, g_xl);
    cudaGetSymbolAddress((void**)&inwh, g_inwh); cudaGetSymbolAddress((void**)&inwl, g_inwl);
    cudaGetSymbolAddress((void**)&xzxh, g_xzxh); cudaGetSymbolAddress((void**)&xzxl, g_xzxl);
    cudaGetSymbolAddress((void**)&cwth, g_cwth); cudaGetSymbolAddress((void**)&cwtl, g_cwtl);
    cudaGetSymbolAddress((void**)&xiah, g_xiah); cudaGetSymbolAddress((void**)&xial, g_xial);
    cudaGetSymbolAddress((void**)&pwh, g_pwh);   cudaGetSymbolAddress((void**)&pwl, g_pwl);
    cudaGetSymbolAddress((void**)&dtah, g_dtah); cudaGetSymbolAddress((void**)&dtal, g_dtal);
    cudaGetSymbolAddress((void**)&dtwh, g_dtwh); cudaGetSymbolAddress((void**)&dtwl, g_dtwl);
    cudaGetSymbolAddress((void**)&yh, g_yh);     cudaGetSymbolAddress((void**)&yl, g_yl);
    cudaGetSymbolAddress((void**)&owh, g_owh);   cudaGetSymbolAddress((void**)&owl, g_owl);

    const int y_elems = NROWS * DMOD;
    const int s_elems = CDIM * DIN * DSTATE;
    float* state_out = (out_size >= y_elems + s_elems) ? (out + y_elems) : nullptr;

    // Launch order: profiled slot (harness offset 2, -s 5) = my launch #3 = conv GEMM
    // 0) fused prep of x / in_w / conv_w
    prep_all<<<(PREP_TOTAL + 255) / 256, 256>>>(x, in_w, conv_w, xh, xl,
                                                inwh, inwl, cwth, cwtl);

    // 1) in-proj: xz = x @ in_w^T + in_b  [4096,2048] fp32 + x-branch hi/lo
    gemm_hmma<<<dim3(2048 / 128, NROWS / 128), 256, GEMM_SMEM>>>(
        xh, xl, inwh, inwl, in_b, p_xz, xzxh, xzxl, NROWS, 2048, DMOD, DIN, 2 | 4);

    // 2) param_w conversion (independent; placed here for profile alignment)
    cvt_hilo<<<(64 * DIN / 4 + 255) / 256, 256>>>(param_w, pwh, pwl, 64 * DIN / 4);

    // 3) conv (direct 4-tap) + bias + gelu -> xiact fp32 AND hi/lo  [4096,1024]
    gemm_hmma<<<dim3(DIN / 128, NROWS / 128), 256, GEMM_SMEM>>>(
        xzxh, xzxl, cwth, cwtl, conv_b, p_xiact, xiah, xial,
        NROWS, DIN, 4 * DIN, DIN, 1 | 2 | 4 | 8);

    // 4) param proj: xdb = xi @ param_w^T + param_b   [4096,64], K=1024
    gemm_hmma<<<dim3(1, NROWS / 128), 256, GEMM_SMEM>>>(
        xiah, xial, pwh, pwl, param_b, p_xdb, nullptr, nullptr, NROWS, 64, DIN, 0, 2);

    // 5-6) dt operand conversions
    cvt_pad<<<(DIN * 64 + 255) / 256, 256>>>(dt_w, dtwh, dtwl, DIN, DDT, DDT, 64);
    cvt_pad<<<(NROWS * 64 + 255) / 256, 256>>>(p_xdb, dtah, dtal, NROWS, 64, DDT, 64);

    // 7) dt proj: dtlin = dt @ dt_w^T + dt_b   [4096,1024], K=64(padded)
    gemm_hmma<<<dim3(DIN / 128, NROWS / 128), 256, GEMM_SMEM>>>(
        dtah, dtal, dtwh, dtwl, dt_b, p_dtlin, nullptr, nullptr, NROWS, DIN, 64, 0, 2);

    // 8) selective scan -> ypre hi/lo + final state
    scan_kernel<<<256, 256>>>(p_xiact, p_xz, p_dtlin, p_xdb, A_log, Dp, ssm0,
                              yh, yl, state_out);

    // 9) out_w conversion
    cvt_hilo<<<(DMOD * DIN / 4 + 255) / 256, 256>>>(out_w, owh, owl, DMOD * DIN / 4);

    // 10) out proj: y @ out_w^T + out_b -> d_out   [4096,512], K=1024
    gemm_hmma<<<dim3(DMOD / 128, NROWS / 128), 256, GEMM_SMEM>>>(
        yh, yl, owh, owl, out_b, out, nullptr, nullptr, NROWS, DMOD, DIN, 0, 2);
}